// round 5
// baseline (speedup 1.0000x reference)
#include <cuda_runtime.h>
#include <cuda_bf16.h>
#include <math.h>

#define NN 30000
#define EE 480000
#define DD 128
#define CAP 96          // padded CSR capacity (Poisson(16): P(deg>96) ~ 1e-40)
#define WPB 8           // warps (=nodes) per agg block; 30000/8 = 3750 exact

// ---------------- static device scratch (zero-initialized at module load) ----------------
__device__ float g_z[NN * DD];
__device__ float g_hout[NN * DD];
__device__ int   g_cursor[NN];          // self-cleaned by agg
__device__ int   g_srcs[NN * CAP];
__device__ float g_stats[2 * DD];       // zeroed by build_kernel block 0 each call

__device__ __forceinline__ float ex2(float x) {
    float r; asm("ex2.approx.f32 %0, %1;" : "=f"(r) : "f"(x)); return r;
}

// ---------------- GEMM (round-3 proven): 64 rows x 128 cols per block ----------------
__global__ void gemm_kernel(const float* __restrict__ h, const float* __restrict__ W) {
    __shared__ float As[64][33];
    __shared__ float Bs[128][33];
    int t = threadIdx.x;
    int tx = t & 31;
    int ty = t >> 5;
    int rowBase = blockIdx.x * 64;

    float acc[8][4];
#pragma unroll
    for (int i = 0; i < 8; i++)
#pragma unroll
        for (int j = 0; j < 4; j++) acc[i][j] = 0.f;

    for (int kc = 0; kc < DD; kc += 32) {
#pragma unroll
        for (int l = 0; l < 8; l++) {
            int lin = t + 256 * l;
            int r = lin >> 5, kk = lin & 31;
            int row = rowBase + r;
            As[r][kk] = (row < NN) ? h[row * DD + kc + kk] : 0.f;
        }
#pragma unroll
        for (int l = 0; l < 16; l++) {
            int lin = t + 256 * l;
            int r = lin >> 5, kk = lin & 31;
            Bs[r][kk] = W[r * DD + kc + kk];
        }
        __syncthreads();
#pragma unroll
        for (int kk = 0; kk < 32; kk++) {
            float a[8], b[4];
#pragma unroll
            for (int i = 0; i < 8; i++) a[i] = As[ty + 8 * i][kk];
#pragma unroll
            for (int j = 0; j < 4; j++) b[j] = Bs[tx + 32 * j][kk];
#pragma unroll
            for (int i = 0; i < 8; i++)
#pragma unroll
                for (int j = 0; j < 4; j++) acc[i][j] = fmaf(a[i], b[j], acc[i][j]);
        }
        __syncthreads();
    }
#pragma unroll
    for (int i = 0; i < 8; i++) {
        int row = rowBase + ty + 8 * i;
        if (row < NN) {
#pragma unroll
            for (int j = 0; j < 4; j++) g_z[row * DD + tx + 32 * j] = acc[i][j];
        }
    }
}

// ---------------- build padded CSR (+ zero BN stats for this invocation) ----------------
__global__ void build_kernel(const int* __restrict__ src, const int* __restrict__ dst) {
    if (blockIdx.x == 0 && threadIdx.x < 2 * DD) g_stats[threadIdx.x] = 0.f;
    int e = blockIdx.x * 256 + threadIdx.x;
    if (e < EE) {
        int d = dst[e];
        int pos = atomicAdd(&g_cursor[d], 1);
        if (pos < CAP) g_srcs[d * CAP + pos] = src[e];
    }
}

// ---------------- agg: warp-per-node, 4-edge MLP, fused BN stats ----------------
__global__ void __launch_bounds__(32 * WPB) agg_kernel(const float* __restrict__ snorm) {
    __shared__ int   ssrc[WPB][CAP];
    __shared__ float shv[WPB][DD];

    int w = threadIdx.x >> 5;
    int lane = threadIdx.x & 31;
    int d = blockIdx.x * WPB + w;

    int deg = g_cursor[d];
    if (deg > CAP) deg = CAP;
    if (lane == 0) g_cursor[d] = 0;          // self-clean for next replay

    for (int i = lane; i < deg; i += 32) ssrc[w][i] = g_srcs[d * CAP + i];

    const float L2E = 1.44269504f;
    float4 zd = *(const float4*)(g_z + d * DD + lane * 4);
    float4 ze;
    ze.x = zd.x * L2E; ze.y = zd.y * L2E; ze.z = zd.z * L2E; ze.w = zd.w * L2E;
    float sn = snorm[d];
    __syncwarp();

    float4 den0 = make_float4(0.f, 0.f, 0.f, 0.f), acc0 = den0;
    float4 den1 = den0, acc1 = den0;

#define PROC(V, DEN, ACC)                                                      \
    { float wt;                                                                \
      wt = ex2(V.x * ze.x); DEN.x += wt; ACC.x = fmaf(wt, V.x, ACC.x);         \
      wt = ex2(V.y * ze.y); DEN.y += wt; ACC.y = fmaf(wt, V.y, ACC.y);         \
      wt = ex2(V.z * ze.z); DEN.z += wt; ACC.z = fmaf(wt, V.z, ACC.z);         \
      wt = ex2(V.w * ze.w); DEN.w += wt; ACC.w = fmaf(wt, V.w, ACC.w); }

    int i = 0;
    for (; i + 4 <= deg; i += 4) {
        int s0 = ssrc[w][i], s1 = ssrc[w][i + 1], s2 = ssrc[w][i + 2], s3 = ssrc[w][i + 3];
        float4 va = *(const float4*)(g_z + s0 * DD + lane * 4);
        float4 vb = *(const float4*)(g_z + s1 * DD + lane * 4);
        float4 vc = *(const float4*)(g_z + s2 * DD + lane * 4);
        float4 vd = *(const float4*)(g_z + s3 * DD + lane * 4);
        PROC(va, den0, acc0);
        PROC(vb, den1, acc1);
        PROC(vc, den0, acc0);
        PROC(vd, den1, acc1);
    }
    for (; i < deg; i++) {
        int s0 = ssrc[w][i];
        float4 va = *(const float4*)(g_z + s0 * DD + lane * 4);
        PROC(va, den0, acc0);
    }
#undef PROC

    den0.x += den1.x; den0.y += den1.y; den0.z += den1.z; den0.w += den1.w;
    acc0.x += acc1.x; acc0.y += acc1.y; acc0.z += acc1.z; acc0.w += acc1.w;

    float4 hv;
    hv.x = (den0.x > 0.f) ? (acc0.x / den0.x) * sn : 0.f;
    hv.y = (den0.y > 0.f) ? (acc0.y / den0.y) * sn : 0.f;
    hv.z = (den0.z > 0.f) ? (acc0.z / den0.z) * sn : 0.f;
    hv.w = (den0.w > 0.f) ? (acc0.w / den0.w) * sn : 0.f;

    *(float4*)(g_hout + d * DD + lane * 4) = hv;
    *(float4*)(&shv[w][lane * 4]) = hv;
    __syncthreads();

    int tid = threadIdx.x;
    int c = tid & (DD - 1);
    if (tid < DD) {
        float s = 0.f;
#pragma unroll
        for (int ww = 0; ww < WPB; ww++) s += shv[ww][c];
        atomicAdd(&g_stats[c], s);
    } else {
        float s2 = 0.f;
#pragma unroll
        for (int ww = 0; ww < WPB; ww++) { float v = shv[ww][c]; s2 = fmaf(v, v, s2); }
        atomicAdd(&g_stats[DD + c], s2);
    }
}

// ---------------- BN apply + ELU (folds stats inline, no finalize launch) ----------------
__global__ void __launch_bounds__(256) apply_kernel(const float* __restrict__ gamma,
                                                    const float* __restrict__ beta,
                                                    float* __restrict__ out) {
    __shared__ float ssc[DD], sbi[DD];
    int t = threadIdx.x;
    if (t < DD) {
        const float invN = 1.f / (float)NN;
        float mu = g_stats[t] * invN;
        float var = g_stats[DD + t] * invN - mu * mu;
        float sc = rsqrtf(var + 1e-5f) * gamma[t];
        ssc[t] = sc;
        sbi[t] = beta[t] - mu * sc;
    }
    __syncthreads();

    int q = blockIdx.x * 256 + t;
    if (q >= NN * DD / 4) return;
    int c4 = (q & 31) * 4;
    float4 hv = *(const float4*)&g_hout[q * 4];
    float4 o;
    float v;
    v = fmaf(hv.x, ssc[c4 + 0], sbi[c4 + 0]); o.x = (v > 0.f) ? v : expm1f(v);
    v = fmaf(hv.y, ssc[c4 + 1], sbi[c4 + 1]); o.y = (v > 0.f) ? v : expm1f(v);
    v = fmaf(hv.z, ssc[c4 + 2], sbi[c4 + 2]); o.z = (v > 0.f) ? v : expm1f(v);
    v = fmaf(hv.w, ssc[c4 + 3], sbi[c4 + 3]); o.w = (v > 0.f) ? v : expm1f(v);
    *(float4*)&out[q * 4] = o;
}

// ---------------- launch ----------------
extern "C" void kernel_launch(void* const* d_in, const int* in_sizes, int n_in,
                              void* d_out, int out_size) {
    const float* h      = (const float*)d_in[0];
    const float* snorm  = (const float*)d_in[1];
    const float* W      = (const float*)d_in[2];
    const float* gamma  = (const float*)d_in[3];
    const float* beta   = (const float*)d_in[4];
    const int*   src    = (const int*)d_in[5];
    const int*   dst    = (const int*)d_in[6];
    float* out = (float*)d_out;

    build_kernel<<<(EE + 255) / 256, 256>>>(src, dst);
    gemm_kernel<<<(NN + 63) / 64, 256>>>(h, W);
    agg_kernel<<<NN / WPB, 32 * WPB>>>(snorm);
    apply_kernel<<<(NN * DD / 4 + 255) / 256, 256>>>(gamma, beta, out);
}

// round 7
// speedup vs baseline: 1.0625x; 1.0625x over previous
#include <cuda_runtime.h>
#include <cuda_bf16.h>
#include <math.h>

#define NN 30000
#define EE 480000
#define DD 128
#define CAP 96          // padded CSR capacity (Poisson(16): P(deg>96) ~ 1e-40)
#define WPB 8           // warps (=nodes) per agg block; 30000/8 = 3750 exact

// ---------------- static device scratch (zero-initialized at module load) ----------------
__device__ float g_z[NN * DD];
__device__ float g_hout[NN * DD];
__device__ int   g_cursor[NN];          // self-cleaned by agg
__device__ int   g_srcs[NN * CAP];
__device__ float g_stats[2 * DD];       // zeroed by build_kernel block 0 each call

__device__ __forceinline__ float ex2(float x) {
    float r; asm("ex2.approx.f32 %0, %1;" : "=f"(r) : "f"(x)); return r;
}

// ---------------- GEMM: 128x128 tile, 8x8 micro-tile, float4 smem (round-4 version) ----------------
__global__ void __launch_bounds__(256) gemm_kernel(const float* __restrict__ h,
                                                   const float* __restrict__ W) {
    __shared__ float As[16][132];
    __shared__ float Bs[16][132];
    int t = threadIdx.x;
    int tx = t & 15;
    int ty = t >> 4;
    int rowBase = blockIdx.x * 128;

    float acc[8][8];
#pragma unroll
    for (int i = 0; i < 8; i++)
#pragma unroll
        for (int j = 0; j < 8; j++) acc[i][j] = 0.f;

    for (int kc = 0; kc < DD; kc += 16) {
#pragma unroll
        for (int l = 0; l < 2; l++) {
            int idx = t + 256 * l;
            int row = idx >> 2, k4 = (idx & 3) * 4;
            int grow = rowBase + row;
            float4 v = (grow < NN) ? *(const float4*)&h[grow * DD + kc + k4]
                                   : make_float4(0.f, 0.f, 0.f, 0.f);
            As[k4 + 0][row] = v.x; As[k4 + 1][row] = v.y;
            As[k4 + 2][row] = v.z; As[k4 + 3][row] = v.w;
        }
#pragma unroll
        for (int l = 0; l < 2; l++) {
            int idx = t + 256 * l;
            int col = idx >> 2, k4 = (idx & 3) * 4;
            float4 v = *(const float4*)&W[col * DD + kc + k4];
            Bs[k4 + 0][col] = v.x; Bs[k4 + 1][col] = v.y;
            Bs[k4 + 2][col] = v.z; Bs[k4 + 3][col] = v.w;
        }
        __syncthreads();
#pragma unroll
        for (int kk = 0; kk < 16; kk++) {
            float4 a0 = *(const float4*)&As[kk][ty * 4];
            float4 a1 = *(const float4*)&As[kk][64 + ty * 4];
            float4 b0 = *(const float4*)&Bs[kk][tx * 4];
            float4 b1 = *(const float4*)&Bs[kk][64 + tx * 4];
            float a[8] = {a0.x, a0.y, a0.z, a0.w, a1.x, a1.y, a1.z, a1.w};
            float b[8] = {b0.x, b0.y, b0.z, b0.w, b1.x, b1.y, b1.z, b1.w};
#pragma unroll
            for (int i = 0; i < 8; i++)
#pragma unroll
                for (int j = 0; j < 8; j++) acc[i][j] = fmaf(a[i], b[j], acc[i][j]);
        }
        __syncthreads();
    }
#pragma unroll
    for (int i = 0; i < 8; i++) {
        int row = rowBase + ((i < 4) ? (ty * 4 + i) : (64 + ty * 4 + i - 4));
        if (row < NN) {
            *(float4*)&g_z[row * DD + tx * 4]      = *(float4*)&acc[i][0];
            *(float4*)&g_z[row * DD + 64 + tx * 4] = *(float4*)&acc[i][4];
        }
    }
}

// ---------------- build padded CSR (+ zero BN stats for this invocation) ----------------
__global__ void build_kernel(const int* __restrict__ src, const int* __restrict__ dst) {
    if (blockIdx.x == 0 && threadIdx.x < 2 * DD) g_stats[threadIdx.x] = 0.f;
    int e = blockIdx.x * 256 + threadIdx.x;
    if (e < EE) {
        int d = dst[e];
        int pos = atomicAdd(&g_cursor[d], 1);
        if (pos < CAP) g_srcs[d * CAP + pos] = src[e];
    }
}

// ---------------- agg: warp-per-node, 2-edge ILP (round-2 measured-good), fused BN stats ----------------
__global__ void __launch_bounds__(32 * WPB) agg_kernel(const float* __restrict__ snorm) {
    __shared__ int   ssrc[WPB][CAP];
    __shared__ float shv[WPB][DD];

    int w = threadIdx.x >> 5;
    int lane = threadIdx.x & 31;
    int d = blockIdx.x * WPB + w;

    int deg = g_cursor[d];
    if (deg > CAP) deg = CAP;
    if (lane == 0) g_cursor[d] = 0;          // self-clean for next replay

    for (int i = lane; i < deg; i += 32) ssrc[w][i] = g_srcs[d * CAP + i];

    const float L2E = 1.44269504f;
    float4 zd = *(const float4*)(g_z + d * DD + lane * 4);
    float4 ze;
    ze.x = zd.x * L2E; ze.y = zd.y * L2E; ze.z = zd.z * L2E; ze.w = zd.w * L2E;
    float sn = snorm[d];
    __syncwarp();

    float4 den = make_float4(0.f, 0.f, 0.f, 0.f);
    float4 acc = make_float4(0.f, 0.f, 0.f, 0.f);
    float4 den2 = make_float4(0.f, 0.f, 0.f, 0.f);
    float4 acc2 = make_float4(0.f, 0.f, 0.f, 0.f);

    int i = 0;
    for (; i + 2 <= deg; i += 2) {
        int s0 = ssrc[w][i];
        int s1 = ssrc[w][i + 1];
        float4 a = *(const float4*)(g_z + s0 * DD + lane * 4);
        float4 b = *(const float4*)(g_z + s1 * DD + lane * 4);
        float w0, w1;
        w0 = ex2(a.x * ze.x); den.x += w0; acc.x = fmaf(w0, a.x, acc.x);
        w1 = ex2(b.x * ze.x); den2.x += w1; acc2.x = fmaf(w1, b.x, acc2.x);
        w0 = ex2(a.y * ze.y); den.y += w0; acc.y = fmaf(w0, a.y, acc.y);
        w1 = ex2(b.y * ze.y); den2.y += w1; acc2.y = fmaf(w1, b.y, acc2.y);
        w0 = ex2(a.z * ze.z); den.z += w0; acc.z = fmaf(w0, a.z, acc.z);
        w1 = ex2(b.z * ze.z); den2.z += w1; acc2.z = fmaf(w1, b.z, acc2.z);
        w0 = ex2(a.w * ze.w); den.w += w0; acc.w = fmaf(w0, a.w, acc.w);
        w1 = ex2(b.w * ze.w); den2.w += w1; acc2.w = fmaf(w1, b.w, acc2.w);
    }
    if (i < deg) {
        int s0 = ssrc[w][i];
        float4 a = *(const float4*)(g_z + s0 * DD + lane * 4);
        float w0;
        w0 = ex2(a.x * ze.x); den.x += w0; acc.x = fmaf(w0, a.x, acc.x);
        w0 = ex2(a.y * ze.y); den.y += w0; acc.y = fmaf(w0, a.y, acc.y);
        w0 = ex2(a.z * ze.z); den.z += w0; acc.z = fmaf(w0, a.z, acc.z);
        w0 = ex2(a.w * ze.w); den.w += w0; acc.w = fmaf(w0, a.w, acc.w);
    }
    den.x += den2.x; den.y += den2.y; den.z += den2.z; den.w += den2.w;
    acc.x += acc2.x; acc.y += acc2.y; acc.z += acc2.z; acc.w += acc2.w;

    float4 hv;
    hv.x = (den.x > 0.f) ? (acc.x / den.x) * sn : 0.f;
    hv.y = (den.y > 0.f) ? (acc.y / den.y) * sn : 0.f;
    hv.z = (den.z > 0.f) ? (acc.z / den.z) * sn : 0.f;
    hv.w = (den.w > 0.f) ? (acc.w / den.w) * sn : 0.f;

    *(float4*)(g_hout + d * DD + lane * 4) = hv;
    *(float4*)(&shv[w][lane * 4]) = hv;
    __syncthreads();

    int tid = threadIdx.x;
    int c = tid & (DD - 1);
    if (tid < DD) {
        float s = 0.f;
#pragma unroll
        for (int ww = 0; ww < WPB; ww++) s += shv[ww][c];
        atomicAdd(&g_stats[c], s);
    } else {
        float s2 = 0.f;
#pragma unroll
        for (int ww = 0; ww < WPB; ww++) { float v = shv[ww][c]; s2 = fmaf(v, v, s2); }
        atomicAdd(&g_stats[DD + c], s2);
    }
}

// ---------------- BN apply + ELU (folds stats inline) ----------------
__global__ void __launch_bounds__(256) apply_kernel(const float* __restrict__ gamma,
                                                    const float* __restrict__ beta,
                                                    float* __restrict__ out) {
    __shared__ float ssc[DD], sbi[DD];
    int t = threadIdx.x;
    if (t < DD) {
        const float invN = 1.f / (float)NN;
        float mu = g_stats[t] * invN;
        float var = g_stats[DD + t] * invN - mu * mu;
        float sc = rsqrtf(var + 1e-5f) * gamma[t];
        ssc[t] = sc;
        sbi[t] = beta[t] - mu * sc;
    }
    __syncthreads();

    int q = blockIdx.x * 256 + t;
    if (q >= NN * DD / 4) return;
    int c4 = (q & 31) * 4;
    float4 hv = *(const float4*)&g_hout[q * 4];
    float4 o;
    float v;
    v = fmaf(hv.x, ssc[c4 + 0], sbi[c4 + 0]); o.x = (v > 0.f) ? v : expm1f(v);
    v = fmaf(hv.y, ssc[c4 + 1], sbi[c4 + 1]); o.y = (v > 0.f) ? v : expm1f(v);
    v = fmaf(hv.z, ssc[c4 + 2], sbi[c4 + 2]); o.z = (v > 0.f) ? v : expm1f(v);
    v = fmaf(hv.w, ssc[c4 + 3], sbi[c4 + 3]); o.w = (v > 0.f) ? v : expm1f(v);
    *(float4*)&out[q * 4] = o;
}

// ---------------- launch ----------------
extern "C" void kernel_launch(void* const* d_in, const int* in_sizes, int n_in,
                              void* d_out, int out_size) {
    const float* h      = (const float*)d_in[0];
    const float* snorm  = (const float*)d_in[1];
    const float* W      = (const float*)d_in[2];
    const float* gamma  = (const float*)d_in[3];
    const float* beta   = (const float*)d_in[4];
    const int*   src    = (const int*)d_in[5];
    const int*   dst    = (const int*)d_in[6];
    float* out = (float*)d_out;

    build_kernel<<<(EE + 255) / 256, 256>>>(src, dst);
    gemm_kernel<<<(NN + 127) / 128, 256>>>(h, W);
    agg_kernel<<<NN / WPB, 32 * WPB>>>(snorm);
    apply_kernel<<<(NN * DD / 4 + 255) / 256, 256>>>(gamma, beta, out);
}